// round 16
// baseline (speedup 1.0000x reference)
#include <cuda_runtime.h>
#include <cuda_bf16.h>
#include <cstdint>

// ---------------------------------------------------------------------------
// Problem constants
// ---------------------------------------------------------------------------
#define HEADS 8
#define DIM   256
#define KVD   512
#define HB    128
#define WB    128
#define HT    64
#define WT    64
#define NPIX  16384
#define NWIN  4096
#define BATCH 4
#define ATT_SCALE 0.17677669529663687f

// ---------------------------------------------------------------------------
// Scratch (device globals)
// ---------------------------------------------------------------------------
__device__ float g_Q [BATCH * NPIX * DIM];   // Q projection (fp32)
__device__ float g_P [BATCH * NPIX * DIM];   // attention output (fp32)
__device__ float g_KV[BATCH * NWIN * KVD];
__device__ float g_E [BATCH * NWIN * HEADS * 16];
__device__ float g_S [BATCH * HEADS * NPIX];

__device__ __nv_bfloat16 g_wqh[DIM * DIM],  g_wql[DIM * DIM];
__device__ __nv_bfloat16 g_wkh[KVD * KVD],  g_wkl[KVD * KVD];
__device__ __nv_bfloat16 g_wph[DIM * DIM],  g_wpl[DIM * DIM];

// ---------------------------------------------------------------------------
// Helpers
// ---------------------------------------------------------------------------
__device__ __forceinline__ uint32_t smem_u32(const void* p) {
    uint32_t a;
    asm("{ .reg .u64 t; cvta.to.shared.u64 t, %1; cvt.u32.u64 %0, t; }"
        : "=r"(a) : "l"(p));
    return a;
}
__device__ __forceinline__ void cpasync16(uint32_t s, const void* g) {
    asm volatile("cp.async.cg.shared.global [%0], [%1], 16;" :: "r"(s), "l"(g));
}
__device__ __forceinline__ void ldm_x4(uint32_t* r, uint32_t addr) {
    asm volatile("ldmatrix.sync.aligned.m8n8.x4.shared.b16 {%0,%1,%2,%3}, [%4];"
                 : "=r"(r[0]), "=r"(r[1]), "=r"(r[2]), "=r"(r[3]) : "r"(addr));
}
__device__ __forceinline__ void mma16816(float* c, const uint32_t* a, const uint32_t* b) {
    asm volatile("mma.sync.aligned.m16n8k16.row.col.f32.bf16.bf16.f32 "
                 "{%0,%1,%2,%3}, {%4,%5,%6,%7}, {%8,%9}, {%0,%1,%2,%3};"
                 : "+f"(c[0]), "+f"(c[1]), "+f"(c[2]), "+f"(c[3])
                 : "r"(a[0]), "r"(a[1]), "r"(a[2]), "r"(a[3]),
                   "r"(b[0]), "r"(b[1]));
}
__device__ __forceinline__ uint32_t sw_off(int r, int c) {
    return (uint32_t)(r * 64 + ((c ^ ((r >> 1) & 3)) << 4));
}

// ---------------------------------------------------------------------------
// Weight split only (1.5 MB total): q_w | kv_w | proj_w
// ---------------------------------------------------------------------------
#define W0 (DIM * DIM / 4)
#define W1 (W0 + KVD * KVD / 4)
#define W2 (W1 + DIM * DIM / 4)

__device__ __forceinline__ void split_elem(const float* src, __nv_bfloat16* ph,
                                           __nv_bfloat16* pl, int k)
{
    float4 v = ((const float4*)src)[k];
    float xs[4] = {v.x, v.y, v.z, v.w};
    unsigned short hb[4], lb[4];
#pragma unroll
    for (int q = 0; q < 4; q++) {
        __nv_bfloat16 h = __float2bfloat16(xs[q]);
        __nv_bfloat16 l = __float2bfloat16(xs[q] - __bfloat162float(h));
        hb[q] = __bfloat16_as_ushort(h);
        lb[q] = __bfloat16_as_ushort(l);
    }
    ((ushort4*)ph)[k] = make_ushort4(hb[0], hb[1], hb[2], hb[3]);
    ((ushort4*)pl)[k] = make_ushort4(lb[0], lb[1], lb[2], lb[3]);
}

__global__ __launch_bounds__(256)
void split_w(const float* __restrict__ qw, const float* __restrict__ kw,
             const float* __restrict__ pw,
             __nv_bfloat16* __restrict__ wqh, __nv_bfloat16* __restrict__ wql,
             __nv_bfloat16* __restrict__ wkh, __nv_bfloat16* __restrict__ wkl,
             __nv_bfloat16* __restrict__ wph, __nv_bfloat16* __restrict__ wpl)
{
    int i0 = (blockIdx.x * blockDim.x + threadIdx.x) * 2;
#pragma unroll
    for (int t = 0; t < 2; t++) {
        int i = i0 + t;
        if (i >= W2) return;
        if (i < W0)      split_elem(qw, wqh, wql, i);
        else if (i < W1) split_elem(kw, wkh, wkl, i - W0);
        else             split_elem(pw, wph, wpl, i - W1);
    }
}

// ---------------------------------------------------------------------------
// HMMA split-bf16 GEMM, A consumed as fp32 with in-kernel hi/lo conversion.
// C[m,n] = sum_k A[m,k]*B[n,k] (+bias[n]); 3 products Ah*Bh + Ah*Bl + Al*Bh.
// Tile 128x128, BK=32, 4 warps (64x64), 3-stage pipeline.
// CRITICAL ORDER: cp.async.wait_group is PER-WARP -> wait must precede the
// block barrier so every warp's B slice is resident before any ldmatrix.
// ---------------------------------------------------------------------------
#define TBM 128
#define TBN 128
#define TBK 32
#define TILE_B   8192                 // one [128 x 64B] bf16 tile
#define STAGE_B  (4 * TILE_B)         // Ah | Al | Bh | Bl
#define NSTAGE   3
#define GEMM_SMEM (NSTAGE * STAGE_B)  // 96 KB

__device__ __forceinline__ void gemm_body_f32a(
    const float* __restrict__ A,
    const __nv_bfloat16* __restrict__ Bhi, const __nv_bfloat16* __restrict__ Blo,
    const float* __restrict__ bias, float* __restrict__ C,
    int N, int K, int bm, int bn, char* dsm)
{
    const uint32_t sbase = smem_u32(dsm);
    const int tid  = threadIdx.x;
    const int wid  = tid >> 5;
    const int lane = tid & 31;
    const int wm   = wid & 1;
    const int wn   = wid >> 1;
    const int KC   = K / TBK;

    float acc[4][8][4];
#pragma unroll
    for (int mi = 0; mi < 4; mi++)
#pragma unroll
        for (int ni = 0; ni < 8; ni++)
#pragma unroll
            for (int q = 0; q < 4; q++) acc[mi][ni][q] = 0.f;

    // B loader (cp.async, one commit per call)
    auto load_b = [&](int ch, int stage) {
        const int k0 = ch * TBK;
        const uint32_t st = sbase + stage * STAGE_B;
#pragma unroll
        for (int t2 = 0; t2 < 4; t2++) {
            const int id = tid + t2 * 128;       // 0..511
            const int r  = id >> 2;
            const int c  = id & 3;
            const uint32_t off = sw_off(r, c);
            const size_t gb = (size_t)(bn + r) * K + k0 + c * 8;
            cpasync16(st + 2 * TILE_B + off, Bhi + gb);
            cpasync16(st + 3 * TILE_B + off, Blo + gb);
        }
        asm volatile("cp.async.commit_group;" ::: "memory");
    };

    // A: thread t owns row bm+t of the tile; 8x float4 per chunk.
    float4 areg[8];
    auto lda = [&](int ch) {
        const float* ga = A + (size_t)(bm + tid) * K + ch * TBK;
#pragma unroll
        for (int i = 0; i < 8; i++) areg[i] = ((const float4*)ga)[i];
    };
    auto sta = [&](int stage) {
        char* base = dsm + stage * STAGE_B;
#pragma unroll
        for (int c = 0; c < 4; c++) {
            float f[8];
            *(float4*)&f[0] = areg[2 * c];
            *(float4*)&f[4] = areg[2 * c + 1];
            uint4 hv, lv;
            unsigned* hp = (unsigned*)&hv;
            unsigned* lp = (unsigned*)&lv;
#pragma unroll
            for (int q = 0; q < 4; q++) {
                const float a0 = f[2 * q], a1 = f[2 * q + 1];
                const __nv_bfloat16 h0 = __float2bfloat16(a0);
                const __nv_bfloat16 h1 = __float2bfloat16(a1);
                const __nv_bfloat16 l0 = __float2bfloat16(a0 - __bfloat162float(h0));
                const __nv_bfloat16 l1 = __float2bfloat16(a1 - __bfloat162float(h1));
                hp[q] = (unsigned)__bfloat16_as_ushort(h0)
                      | ((unsigned)__bfloat16_as_ushort(h1) << 16);
                lp[q] = (unsigned)__bfloat16_as_ushort(l0)
                      | ((unsigned)__bfloat16_as_ushort(l1) << 16);
            }
            const uint32_t off = sw_off(tid, c);
            *(uint4*)(base + 0 * TILE_B + off) = hv;
            *(uint4*)(base + 1 * TILE_B + off) = lv;
        }
    };

    // one ks-half of the MMA work for chunk in stage address `st`
    auto compute_half = [&](uint32_t st, int ks) {
        uint32_t ah[4][4], al[4][4];
#pragma unroll
        for (int mi = 0; mi < 4; mi++) {
            const int r = wm * 64 + mi * 16 + ((lane >> 3) & 1) * 8 + (lane & 7);
            const int c = ks * 2 + (lane >> 4);
            const uint32_t off = sw_off(r, c);
            ldm_x4(ah[mi], st + 0 * TILE_B + off);
            ldm_x4(al[mi], st + 1 * TILE_B + off);
        }
#pragma unroll
        for (int g = 0; g < 4; g++) {
            const int r = wn * 64 + g * 16 + ((lane >> 4) & 1) * 8 + (lane & 7);
            const int c = ks * 2 + ((lane >> 3) & 1);
            const uint32_t off = sw_off(r, c);
            uint32_t th[4], tl[4];
            ldm_x4(th, st + 2 * TILE_B + off);
            ldm_x4(tl, st + 3 * TILE_B + off);
#pragma unroll
            for (int mi = 0; mi < 4; mi++) {
                mma16816(acc[mi][2 * g],     ah[mi], th);
                mma16816(acc[mi][2 * g],     ah[mi], tl);
                mma16816(acc[mi][2 * g],     al[mi], th);
                mma16816(acc[mi][2 * g + 1], ah[mi], th + 2);
                mma16816(acc[mi][2 * g + 1], ah[mi], tl + 2);
                mma16816(acc[mi][2 * g + 1], al[mi], th + 2);
            }
        }
    };

    // prologue: A stages 0,1 converted+stored; B stages 0,1 in flight
    lda(0); sta(0);
    lda(1); sta(1);
    load_b(0, 0);
    load_b(1, 1);

    for (int ch = 0; ch < KC; ch++) {
        // my own B(ch) slice complete (one newer group may be pending)
        asm volatile("cp.async.wait_group 1;" ::: "memory");
        // ALL warps' waits done -> full B(ch) tile resident & visible;
        // also proves every warp finished reading stage (ch-1)%3
        __syncthreads();

        const bool pre = (ch + 2 < KC);
        if (pre) {
            lda(ch + 2);                          // LDG in flight during ks0
            load_b(ch + 2, (ch + 2) % NSTAGE);    // overwrites stage (ch-1)%3
        } else {
            asm volatile("cp.async.commit_group;" ::: "memory");
        }

        const uint32_t st = sbase + (ch % NSTAGE) * STAGE_B;
        compute_half(st, 0);
        if (pre) sta((ch + 2) % NSTAGE);          // stage (ch-1)%3, post-barrier safe
        compute_half(st, 1);
    }

    const int rbase = bm + wm * 64 + (lane >> 2);
    const int cbase = bn + wn * 64 + (lane & 3) * 2;
#pragma unroll
    for (int mi = 0; mi < 4; mi++) {
#pragma unroll
        for (int ni = 0; ni < 8; ni++) {
            const int col = cbase + ni * 8;
            float b0 = 0.f, b1 = 0.f;
            if (bias) { b0 = __ldg(bias + col); b1 = __ldg(bias + col + 1); }
            float* p0 = C + (size_t)(rbase + mi * 16) * N + col;
            float* p1 = C + (size_t)(rbase + mi * 16 + 8) * N + col;
            *(float2*)p0 = make_float2(acc[mi][ni][0] + b0, acc[mi][ni][1] + b1);
            *(float2*)p1 = make_float2(acc[mi][ni][2] + b0, acc[mi][ni][3] + b1);
        }
    }
}

// Fused KV-GEMM (long tiles first, LPT) + Q-GEMM, single stream.
#define QBLKS  ((BATCH * NPIX / TBM) * (DIM / TBN))   // 1024
#define KVBLKS ((BATCH * NWIN / TBM) * (KVD / TBN))   // 512

__global__ __launch_bounds__(128, 2)
void gemm_qkv(const float* __restrict__ Xt,
              const __nv_bfloat16* __restrict__ wkh, const __nv_bfloat16* __restrict__ wkl,
              const float* __restrict__ Xb,
              const __nv_bfloat16* __restrict__ wqh, const __nv_bfloat16* __restrict__ wql,
              float* __restrict__ Q, float* __restrict__ KV)
{
    extern __shared__ char dsm[];
    const int bid = blockIdx.x;
    if (bid < KVBLKS) {
        gemm_body_f32a(Xt, wkh, wkl, nullptr, KV,
                       KVD, KVD, (bid >> 2) * TBM, (bid & 3) * TBN, dsm);
    } else {
        const int t = bid - KVBLKS;
        gemm_body_f32a(Xb, wqh, wql, nullptr, Q,
                       DIM, DIM, (t >> 1) * TBM, (t & 1) * TBN, dsm);
    }
}

__global__ __launch_bounds__(128, 2)
void gemm_proj(const float* __restrict__ P,
               const __nv_bfloat16* __restrict__ wph, const __nv_bfloat16* __restrict__ wpl,
               const float* __restrict__ bias, float* __restrict__ C)
{
    extern __shared__ char dsm[];
    gemm_body_f32a(P, wph, wpl, bias, C,
                   DIM, DIM, (int)blockIdx.y * TBM, (int)blockIdx.x * TBN, dsm);
}

// ---------------------------------------------------------------------------
// Covering-window enumeration
// ---------------------------------------------------------------------------
__device__ __forceinline__ int covers(int r, int lim, int tys[2], int iis[2])
{
    const int th = (r + 1) >> 1;
    const int ih = (r + 1) & 1;
    int n = 0;
    if (th < lim) { tys[n] = th;     iis[n] = ih;     n++; }
    if (th >= 1)  { tys[n] = th - 1; iis[n] = ih + 2; n++; }
    return n;
}

// ---------------------------------------------------------------------------
// Phase 1 (warp per pixel): exp(logits) -> g_E, per-(head,pixel) sums -> g_S
// ---------------------------------------------------------------------------
__global__ __launch_bounds__(256)
void attn_phase1(const float* __restrict__ Q, const float* __restrict__ KV,
                 const float* __restrict__ rel_init,
                 const float* __restrict__ rel_bias)
{
    __shared__ float s_rel[16];
    if (threadIdx.x < 16)
        s_rel[threadIdx.x] = rel_init[threadIdx.x] + rel_bias[threadIdx.x];
    __syncthreads();

    const int wrp  = threadIdx.x >> 5;
    const int lane = threadIdx.x & 31;
    const int pix  = blockIdx.x * 8 + wrp;
    const int b    = pix >> 14;
    const int rc   = pix & (NPIX - 1);
    const int r    = rc >> 7;
    const int c    = rc & (WB - 1);
    const int h    = lane >> 2;
    const int l4   = lane & 3;
    const int ch   = h * 32 + l4 * 8;

    const float* qp = Q + (uint32_t)pix * DIM + ch;
    const float4 q0 = *(const float4*)qp;
    const float4 q1 = *(const float4*)(qp + 4);
    const float* kvbase = KV + (uint32_t)b * (NWIN * KVD) + ch;

    int tys[2], iis[2], txs[2], jjs[2];
    const int nty = covers(r, HT, tys, iis);
    const int ntx = covers(c, WT, txs, jjs);

    float ssum = 0.f;
#pragma unroll
    for (int a = 0; a < 2; a++) {
        if (a >= nty) break;
#pragma unroll
        for (int e = 0; e < 2; e++) {
            if (e >= ntx) break;
            const int w = tys[a] * WT + txs[e];
            const int p = iis[a] * 4 + jjs[e];
            const float* kp = kvbase + w * KVD;
            const float4 k0 = *(const float4*)kp;
            const float4 k1 = *(const float4*)(kp + 4);
            float part = q0.x * k0.x + q0.y * k0.y + q0.z * k0.z + q0.w * k0.w
                       + q1.x * k1.x + q1.y * k1.y + q1.z * k1.z + q1.w * k1.w;
            part += __shfl_xor_sync(0xffffffffu, part, 2);
            part += __shfl_xor_sync(0xffffffffu, part, 1);
            const float ex = expf(part * ATT_SCALE + s_rel[p]);
            ssum += ex;
            if (l4 == 0)
                g_E[(uint32_t)((b * NWIN + w) * HEADS + h) * 16 + p] = ex;
        }
    }
    if (l4 == 0)
        g_S[(uint32_t)(b * HEADS + h) * NPIX + rc] = ssum;
}

// ---------------------------------------------------------------------------
// Phase 2 (warp per pixel, shfl exchange, no smem/barrier): writes fp32 P.
// Scrambled divisor faithful to the reference reshape. OOB slots -> wgt=0.
// ---------------------------------------------------------------------------
__global__ __launch_bounds__(256)
void attn_phase2(const float* __restrict__ KV, float* __restrict__ P)
{
    const int wrp  = threadIdx.x >> 5;
    const int lane = threadIdx.x & 31;
    const int pix  = blockIdx.x * 8 + wrp;
    const int b    = pix >> 14;
    const int rc   = pix & (NPIX - 1);
    const int r    = rc >> 7;
    const int c    = rc & (WB - 1);

    int tys[2], iis[2], txs[2], jjs[2];
    const int nty = covers(r, HT, tys, iis);
    const int ntx = covers(c, WT, txs, jjs);

    const int slot = lane >> 3;
    const int sh   = lane & 7;
    const int sa   = slot >> 1;
    const int se   = slot & 1;
    float wgt = 0.f;
    int   wofs = 0;
    if (sa < nty && se < ntx) {
        const int w = tys[sa] * WT + txs[se];
        const int p = iis[sa] * 4 + jjs[se];
        const float ex = g_E[(uint32_t)((b * NWIN + w) * HEADS + sh) * 16 + p];
        const int h2 = w >> 9;
        const int w2 = ((w & 511) << 3) + sh;
        const int r2 = 2 * (w2 >> 6) - 1 + (p >> 2);
        const int c2 = 2 * (w2 & 63) - 1 + (p & 3);
        float denom = 1.f;
        if ((unsigned)r2 < (unsigned)HB && (unsigned)c2 < (unsigned)WB)
            denom = g_S[(uint32_t)(b * HEADS + h2) * NPIX + r2 * WB + c2];
        wgt = ex / denom;
        wofs = w * KVD;
    }

    const int my_h = lane >> 2;
    float w0 = __shfl_sync(0xffffffffu, wgt, my_h);
    float w1 = __shfl_sync(0xffffffffu, wgt, 8 + my_h);
    float w2_ = __shfl_sync(0xffffffffu, wgt, 16 + my_h);
    float w3 = __shfl_sync(0xffffffffu, wgt, 24 + my_h);
    int o0 = __shfl_sync(0xffffffffu, wofs, 0);
    int o1 = __shfl_sync(0xffffffffu, wofs, 8);
    int o2 = __shfl_sync(0xffffffffu, wofs, 16);
    int o3 = __shfl_sync(0xffffffffu, wofs, 24);

    const float* vbase = KV + (uint32_t)b * (NWIN * KVD) + DIM + lane * 8;
    float4 oa = make_float4(0.f, 0.f, 0.f, 0.f);
    float4 ob = make_float4(0.f, 0.f, 0.f, 0.f);
#pragma unroll
    for (int s = 0; s < 4; s++) {
        const float wg = (s == 0) ? w0 : (s == 1) ? w1 : (s == 2) ? w2_ : w3;
        const int   of = (s == 0) ? o0 : (s == 1) ? o1 : (s == 2) ? o2 : o3;
        const float4 va = *(const float4*)(vbase + of);
        const float4 vb = *(const float4*)(vbase + of + 4);
        oa.x = fmaf(wg, va.x, oa.x); oa.y = fmaf(wg, va.y, oa.y);
        oa.z = fmaf(wg, va.z, oa.z); oa.w = fmaf(wg, va.w, oa.w);
        ob.x = fmaf(wg, vb.x, ob.x); ob.y = fmaf(wg, vb.y, ob.y);
        ob.z = fmaf(wg, vb.z, ob.z); ob.w = fmaf(wg, vb.w, ob.w);
    }

    float* pp = P + (uint32_t)pix * DIM + lane * 8;
    *(float4*)pp       = oa;
    *(float4*)(pp + 4) = ob;
}

// ---------------------------------------------------------------------------
// Launch (single stream)
// ---------------------------------------------------------------------------
extern "C" void kernel_launch(void* const* d_in, const int* in_sizes, int n_in,
                              void* d_out, int out_size)
{
    (void)in_sizes; (void)n_in; (void)out_size;
    const float* Xt       = (const float*)d_in[0];
    const float* Xb       = (const float*)d_in[1];
    const float* q_w      = (const float*)d_in[2];
    const float* kv_w     = (const float*)d_in[3];
    const float* proj_w   = (const float*)d_in[4];
    const float* proj_b   = (const float*)d_in[5];
    const float* rel_init = (const float*)d_in[6];
    const float* rel_bias = (const float*)d_in[7];
    float* out = (float*)d_out;

    float *Qb, *Pb, *KVb;
    __nv_bfloat16 *wqh, *wql, *wkh, *wkl, *wph, *wpl;
    cudaGetSymbolAddress((void**)&Qb,  g_Q);
    cudaGetSymbolAddress((void**)&Pb,  g_P);
    cudaGetSymbolAddress((void**)&KVb, g_KV);
    cudaGetSymbolAddress((void**)&wqh, g_wqh);
    cudaGetSymbolAddress((void**)&wql, g_wql);
    cudaGetSymbolAddress((void**)&wkh, g_wkh);
    cudaGetSymbolAddress((void**)&wkl, g_wkl);
    cudaGetSymbolAddress((void**)&wph, g_wph);
    cudaGetSymbolAddress((void**)&wpl, g_wpl);

    cudaFuncSetAttribute(gemm_qkv,
                         cudaFuncAttributeMaxDynamicSharedMemorySize, GEMM_SMEM);
    cudaFuncSetAttribute(gemm_proj,
                         cudaFuncAttributeMaxDynamicSharedMemorySize, GEMM_SMEM);

    // weight splits only (~1.5 MB)
    split_w<<<(W2 / 2 + 255) / 256, 256>>>(q_w, kv_w, proj_w,
                                           wqh, wql, wkh, wkl, wph, wpl);

    // 1+2) KV = Xt @ kv_w^T (long tiles first) and Q = Xb @ q_w^T, fp32 A
    gemm_qkv<<<QBLKS + KVBLKS, 128, GEMM_SMEM>>>(
        Xt, wkh, wkl, Xb, wqh, wql, Qb, KVb);

    // 3) attention numerators + sums (warp per pixel)
    attn_phase1<<<(BATCH * NPIX) / 8, 256>>>(Qb, KVb, rel_init, rel_bias);

    // 4) normalization + V + fold (warp per pixel, fp32 P)
    attn_phase2<<<(BATCH * NPIX) / 8, 256>>>(KVb, Pb);

    // 5) Out = P @ proj_w^T + proj_b, fp32 A
    gemm_proj<<<dim3(DIM / TBN, (BATCH * NPIX) / TBM), 128, GEMM_SMEM>>>(
        Pb, wph, wpl, proj_b, out);
}

// round 17
// speedup vs baseline: 1.2077x; 1.2077x over previous
#include <cuda_runtime.h>
#include <cuda_bf16.h>
#include <cstdint>

// ---------------------------------------------------------------------------
// Problem constants
// ---------------------------------------------------------------------------
#define HEADS 8
#define DIM   256
#define KVD   512
#define HB    128
#define WB    128
#define HT    64
#define WT    64
#define NPIX  16384
#define NWIN  4096
#define BATCH 4
#define ATT_SCALE 0.17677669529663687f

// ---------------------------------------------------------------------------
// Scratch (device globals)
// ---------------------------------------------------------------------------
__device__ float g_Q [BATCH * NPIX * DIM];
__device__ float g_KV[BATCH * NWIN * KVD];
__device__ float g_E [BATCH * NWIN * HEADS * 16];
__device__ float g_S [BATCH * HEADS * NPIX];

__device__ __nv_bfloat16 g_Xbh[BATCH * NPIX * DIM];
__device__ __nv_bfloat16 g_Xbl[BATCH * NPIX * DIM];
__device__ __nv_bfloat16 g_Xth[BATCH * NWIN * KVD];
__device__ __nv_bfloat16 g_Xtl[BATCH * NWIN * KVD];
__device__ __nv_bfloat16 g_Ph [BATCH * NPIX * DIM];
__device__ __nv_bfloat16 g_Pl [BATCH * NPIX * DIM];
__device__ __nv_bfloat16 g_wqh[DIM * DIM],  g_wql[DIM * DIM];
__device__ __nv_bfloat16 g_wkh[KVD * KVD],  g_wkl[KVD * KVD];
__device__ __nv_bfloat16 g_wph[DIM * DIM],  g_wpl[DIM * DIM];

// ---------------------------------------------------------------------------
// Helpers
// ---------------------------------------------------------------------------
__device__ __forceinline__ uint32_t smem_u32(const void* p) {
    uint32_t a;
    asm("{ .reg .u64 t; cvta.to.shared.u64 t, %1; cvt.u32.u64 %0, t; }"
        : "=r"(a) : "l"(p));
    return a;
}
__device__ __forceinline__ void cpasync16(uint32_t s, const void* g) {
    asm volatile("cp.async.cg.shared.global [%0], [%1], 16;" :: "r"(s), "l"(g));
}
__device__ __forceinline__ void ldm_x4(uint32_t* r, uint32_t addr) {
    asm volatile("ldmatrix.sync.aligned.m8n8.x4.shared.b16 {%0,%1,%2,%3}, [%4];"
                 : "=r"(r[0]), "=r"(r[1]), "=r"(r[2]), "=r"(r[3]) : "r"(addr));
}
__device__ __forceinline__ void mma16816(float* c, const uint32_t* a, const uint32_t* b) {
    asm volatile("mma.sync.aligned.m16n8k16.row.col.f32.bf16.bf16.f32 "
                 "{%0,%1,%2,%3}, {%4,%5,%6,%7}, {%8,%9}, {%0,%1,%2,%3};"
                 : "+f"(c[0]), "+f"(c[1]), "+f"(c[2]), "+f"(c[3])
                 : "r"(a[0]), "r"(a[1]), "r"(a[2]), "r"(a[3]),
                   "r"(b[0]), "r"(b[1]));
}
// swizzled byte offset of (row r, 16B-chunk c) inside a [rows x 64B] tile
__device__ __forceinline__ uint32_t sw_off(int r, int c) {
    return (uint32_t)(r * 64 + ((c ^ ((r >> 1) & 3)) << 4));
}

// ---------------------------------------------------------------------------
// Fused split: all five fp32 -> (hi,lo) bf16 conversions, 2 float4/thread.
// ---------------------------------------------------------------------------
#define S0 (BATCH * NPIX * DIM / 4)
#define S1 (S0 + BATCH * NWIN * KVD / 4)
#define S2 (S1 + DIM * DIM / 4)
#define S3 (S2 + KVD * KVD / 4)
#define S4 (S3 + DIM * DIM / 4)

__device__ __forceinline__ void split_one(int i,
    const float* Xb, const float* Xt, const float* qw, const float* kw,
    const float* pw,
    __nv_bfloat16* Xbh, __nv_bfloat16* Xbl, __nv_bfloat16* Xth, __nv_bfloat16* Xtl,
    __nv_bfloat16* wqh, __nv_bfloat16* wql, __nv_bfloat16* wkh, __nv_bfloat16* wkl,
    __nv_bfloat16* wph, __nv_bfloat16* wpl)
{
    const float* src; __nv_bfloat16 *ph, *pl; int base;
    if (i < S0)      { src = Xb; ph = Xbh; pl = Xbl; base = 0;  }
    else if (i < S1) { src = Xt; ph = Xth; pl = Xtl; base = S0; }
    else if (i < S2) { src = qw; ph = wqh; pl = wql; base = S1; }
    else if (i < S3) { src = kw; ph = wkh; pl = wkl; base = S2; }
    else             { src = pw; ph = wph; pl = wpl; base = S3; }
    const int k = i - base;
    float4 v = ((const float4*)src)[k];
    float xs[4] = {v.x, v.y, v.z, v.w};
    unsigned short hb[4], lb[4];
#pragma unroll
    for (int q = 0; q < 4; q++) {
        __nv_bfloat16 h = __float2bfloat16(xs[q]);
        __nv_bfloat16 l = __float2bfloat16(xs[q] - __bfloat162float(h));
        hb[q] = __bfloat16_as_ushort(h);
        lb[q] = __bfloat16_as_ushort(l);
    }
    ((ushort4*)ph)[k] = make_ushort4(hb[0], hb[1], hb[2], hb[3]);
    ((ushort4*)pl)[k] = make_ushort4(lb[0], lb[1], lb[2], lb[3]);
}

__global__ __launch_bounds__(256)
void split_all(const float* __restrict__ Xb, const float* __restrict__ Xt,
               const float* __restrict__ qw, const float* __restrict__ kw,
               const float* __restrict__ pw,
               __nv_bfloat16* __restrict__ Xbh, __nv_bfloat16* __restrict__ Xbl,
               __nv_bfloat16* __restrict__ Xth, __nv_bfloat16* __restrict__ Xtl,
               __nv_bfloat16* __restrict__ wqh, __nv_bfloat16* __restrict__ wql,
               __nv_bfloat16* __restrict__ wkh, __nv_bfloat16* __restrict__ wkl,
               __nv_bfloat16* __restrict__ wph, __nv_bfloat16* __restrict__ wpl)
{
    int i0 = (blockIdx.x * blockDim.x + threadIdx.x) * 2;
    if (i0 < S4)
        split_one(i0, Xb, Xt, qw, kw, pw, Xbh, Xbl, Xth, Xtl,
                  wqh, wql, wkh, wkl, wph, wpl);
    if (i0 + 1 < S4)
        split_one(i0 + 1, Xb, Xt, qw, kw, pw, Xbh, Xbl, Xth, Xtl,
                  wqh, wql, wkh, wkl, wph, wpl);
}

// ---------------------------------------------------------------------------
// HMMA split-bf16 GEMM body (round-11): C = A*B^T (+bias), pre-split bf16.
// Tile 128x128, BK=32, 4 warps (64x64), 3-stage cp.async, 2 CTAs/SM.
// ---------------------------------------------------------------------------
#define TBM 128
#define TBN 128
#define TBK 32
#define TILE_B   8192
#define STAGE_B  (4 * TILE_B)
#define NSTAGE   3
#define GEMM_SMEM (NSTAGE * STAGE_B)   // 96 KB

__device__ __forceinline__ void gemm_body(
    const __nv_bfloat16* __restrict__ Ahi, const __nv_bfloat16* __restrict__ Alo,
    const __nv_bfloat16* __restrict__ Bhi, const __nv_bfloat16* __restrict__ Blo,
    const float* __restrict__ bias, float* __restrict__ C,
    int N, int K, int bm, int bn, char* dsm)
{
    const uint32_t sbase = smem_u32(dsm);
    const int tid  = threadIdx.x;
    const int wid  = tid >> 5;
    const int lane = tid & 31;
    const int wm   = wid & 1;
    const int wn   = wid >> 1;
    const int KC   = K / TBK;

    float acc[4][8][4];
#pragma unroll
    for (int mi = 0; mi < 4; mi++)
#pragma unroll
        for (int ni = 0; ni < 8; ni++)
#pragma unroll
            for (int q = 0; q < 4; q++) acc[mi][ni][q] = 0.f;

    auto load_chunk = [&](int ch, int stage) {
        const int k0 = ch * TBK;
        const uint32_t st = sbase + stage * STAGE_B;
#pragma unroll
        for (int t2 = 0; t2 < 4; t2++) {
            const int id = tid + t2 * 128;
            const int r  = id >> 2;
            const int c  = id & 3;
            const uint32_t off = sw_off(r, c);
            const size_t ga = (size_t)(bm + r) * K + k0 + c * 8;
            const size_t gb = (size_t)(bn + r) * K + k0 + c * 8;
            cpasync16(st + 0 * TILE_B + off, Ahi + ga);
            cpasync16(st + 1 * TILE_B + off, Alo + ga);
            cpasync16(st + 2 * TILE_B + off, Bhi + gb);
            cpasync16(st + 3 * TILE_B + off, Blo + gb);
        }
        asm volatile("cp.async.commit_group;" ::: "memory");
    };

    load_chunk(0, 0);
    load_chunk(1, 1);

    for (int ch = 0; ch < KC; ch++) {
        asm volatile("cp.async.wait_group 1;" ::: "memory");   // chunk ch resident
        __syncthreads();                                       // all warps past ch-1
        if (ch + 2 < KC) load_chunk(ch + 2, (ch + 2) % NSTAGE);
        else asm volatile("cp.async.commit_group;" ::: "memory");

        const uint32_t st = sbase + (ch % NSTAGE) * STAGE_B;
#pragma unroll
        for (int ks = 0; ks < 2; ks++) {
            uint32_t ah[4][4], al[4][4];
#pragma unroll
            for (int mi = 0; mi < 4; mi++) {
                const int r = wm * 64 + mi * 16 + ((lane >> 3) & 1) * 8 + (lane & 7);
                const int c = ks * 2 + (lane >> 4);
                const uint32_t off = sw_off(r, c);
                ldm_x4(ah[mi], st + 0 * TILE_B + off);
                ldm_x4(al[mi], st + 1 * TILE_B + off);
            }
#pragma unroll
            for (int g = 0; g < 4; g++) {
                const int r = wn * 64 + g * 16 + ((lane >> 4) & 1) * 8 + (lane & 7);
                const int c = ks * 2 + ((lane >> 3) & 1);
                const uint32_t off = sw_off(r, c);
                uint32_t th[4], tl[4];
                ldm_x4(th, st + 2 * TILE_B + off);
                ldm_x4(tl, st + 3 * TILE_B + off);
#pragma unroll
                for (int mi = 0; mi < 4; mi++) {
                    mma16816(acc[mi][2 * g],     ah[mi], th);
                    mma16816(acc[mi][2 * g],     ah[mi], tl);
                    mma16816(acc[mi][2 * g],     al[mi], th);
                    mma16816(acc[mi][2 * g + 1], ah[mi], th + 2);
                    mma16816(acc[mi][2 * g + 1], ah[mi], tl + 2);
                    mma16816(acc[mi][2 * g + 1], al[mi], th + 2);
                }
            }
        }
    }

    const int rbase = bm + wm * 64 + (lane >> 2);
    const int cbase = bn + wn * 64 + (lane & 3) * 2;
#pragma unroll
    for (int mi = 0; mi < 4; mi++) {
#pragma unroll
        for (int ni = 0; ni < 8; ni++) {
            const int col = cbase + ni * 8;
            float b0 = 0.f, b1 = 0.f;
            if (bias) { b0 = __ldg(bias + col); b1 = __ldg(bias + col + 1); }
            float* p0 = C + (size_t)(rbase + mi * 16) * N + col;
            float* p1 = C + (size_t)(rbase + mi * 16 + 8) * N + col;
            *(float2*)p0 = make_float2(acc[mi][ni][0] + b0, acc[mi][ni][1] + b1);
            *(float2*)p1 = make_float2(acc[mi][ni][2] + b0, acc[mi][ni][3] + b1);
        }
    }
}

// Fused KV-GEMM (long tiles FIRST, LPT) + Q-GEMM.
#define QBLKS  ((BATCH * NPIX / TBM) * (DIM / TBN))   // 1024
#define KVBLKS ((BATCH * NWIN / TBM) * (KVD / TBN))   // 512

__global__ __launch_bounds__(128, 2)
void gemm_qkv(const __nv_bfloat16* __restrict__ Xbh, const __nv_bfloat16* __restrict__ Xbl,
              const __nv_bfloat16* __restrict__ wqh, const __nv_bfloat16* __restrict__ wql,
              const __nv_bfloat16* __restrict__ Xth, const __nv_bfloat16* __restrict__ Xtl,
              const __nv_bfloat16* __restrict__ wkh, const __nv_bfloat16* __restrict__ wkl,
              float* __restrict__ Q, float* __restrict__ KV)
{
    extern __shared__ char dsm[];
    const int bid = blockIdx.x;
    if (bid < KVBLKS) {
        gemm_body(Xth, Xtl, wkh, wkl, nullptr, KV,
                  KVD, KVD, (bid >> 2) * TBM, (bid & 3) * TBN, dsm);
    } else {
        const int t = bid - KVBLKS;
        gemm_body(Xbh, Xbl, wqh, wql, nullptr, Q,
                  DIM, DIM, (t >> 1) * TBM, (t & 1) * TBN, dsm);
    }
}

// ---------------------------------------------------------------------------
// proj GEMM variant: TBN=64 (grid 4x512 = 2048 CTAs -> small tail, 3 CTAs/SM).
// Same chunk/ks/product order as gemm_body -> bit-identical results.
// Stage: Ah(8K) | Al(8K) | Bh(4K) | Bl(4K) = 24KB, 3 stages = 72KB.
// ---------------------------------------------------------------------------
#define PTBN 64
#define P_AT 8192
#define P_BT 4096
#define P_STAGE (2 * P_AT + 2 * P_BT)        // 24 KB
#define PROJ_SMEM (NSTAGE * P_STAGE)          // 72 KB

__global__ __launch_bounds__(128)
void gemm_proj(const __nv_bfloat16* __restrict__ Ahi, const __nv_bfloat16* __restrict__ Alo,
               const __nv_bfloat16* __restrict__ Bhi, const __nv_bfloat16* __restrict__ Blo,
               const float* __restrict__ bias, float* __restrict__ C)
{
    extern __shared__ char dsm[];
    const uint32_t sbase = smem_u32(dsm);
    const int N = DIM, K = DIM;
    const int bm = blockIdx.y * TBM;
    const int bn = blockIdx.x * PTBN;        // x = N -> adjacent CTAs share A (L2)
    const int tid  = threadIdx.x;
    const int wid  = tid >> 5;
    const int lane = tid & 31;
    const int wm   = wid & 1;                // 2 warps M (64 rows)
    const int wn   = wid >> 1;               // 2 warps N (32 cols)
    const int KC   = K / TBK;                // 8

    float acc[4][4][4];
#pragma unroll
    for (int mi = 0; mi < 4; mi++)
#pragma unroll
        for (int ni = 0; ni < 4; ni++)
#pragma unroll
            for (int q = 0; q < 4; q++) acc[mi][ni][q] = 0.f;

    auto load_chunk = [&](int ch, int stage) {
        const int k0 = ch * TBK;
        const uint32_t st = sbase + stage * P_STAGE;
        // A: 128 rows x 4 chunks
#pragma unroll
        for (int t2 = 0; t2 < 4; t2++) {
            const int id = tid + t2 * 128;
            const int r  = id >> 2;
            const int c  = id & 3;
            const uint32_t off = sw_off(r, c);
            const size_t ga = (size_t)(bm + r) * K + k0 + c * 8;
            cpasync16(st + 0 * P_AT + off, Ahi + ga);
            cpasync16(st + 1 * P_AT + off, Alo + ga);
        }
        // B: 64 rows x 4 chunks
#pragma unroll
        for (int t2 = 0; t2 < 2; t2++) {
            const int id = tid + t2 * 128;
            const int r  = id >> 2;
            const int c  = id & 3;
            const uint32_t off = sw_off(r, c);
            const size_t gb = (size_t)(bn + r) * K + k0 + c * 8;
            cpasync16(st + 2 * P_AT + 0 * P_BT + off, Bhi + gb);
            cpasync16(st + 2 * P_AT + 1 * P_BT + off, Blo + gb);
        }
        asm volatile("cp.async.commit_group;" ::: "memory");
    };

    load_chunk(0, 0);
    load_chunk(1, 1);

    for (int ch = 0; ch < KC; ch++) {
        asm volatile("cp.async.wait_group 1;" ::: "memory");
        __syncthreads();
        if (ch + 2 < KC) load_chunk(ch + 2, (ch + 2) % NSTAGE);
        else asm volatile("cp.async.commit_group;" ::: "memory");

        const uint32_t st = sbase + (ch % NSTAGE) * P_STAGE;
#pragma unroll
        for (int ks = 0; ks < 2; ks++) {
            uint32_t ah[4][4], al[4][4];
#pragma unroll
            for (int mi = 0; mi < 4; mi++) {
                const int r = wm * 64 + mi * 16 + ((lane >> 3) & 1) * 8 + (lane & 7);
                const int c = ks * 2 + (lane >> 4);
                const uint32_t off = sw_off(r, c);
                ldm_x4(ah[mi], st + 0 * P_AT + off);
                ldm_x4(al[mi], st + 1 * P_AT + off);
            }
#pragma unroll
            for (int g = 0; g < 2; g++) {
                const int r = wn * 32 + g * 16 + ((lane >> 4) & 1) * 8 + (lane & 7);
                const int c = ks * 2 + ((lane >> 3) & 1);
                const uint32_t off = sw_off(r, c);
                uint32_t th[4], tl[4];
                ldm_x4(th, st + 2 * P_AT + 0 * P_BT + off);
                ldm_x4(tl, st + 2 * P_AT + 1 * P_BT + off);
#pragma unroll
                for (int mi = 0; mi < 4; mi++) {
                    mma16816(acc[mi][2 * g],     ah[mi], th);
                    mma16816(acc[mi][2 * g],     ah[mi], tl);
                    mma16816(acc[mi][2 * g],     al[mi], th);
                    mma16816(acc[mi][2 * g + 1], ah[mi], th + 2);
                    mma16816(acc[mi][2 * g + 1], ah[mi], tl + 2);
                    mma16816(acc[mi][2 * g + 1], al[mi], th + 2);
                }
            }
        }
    }

    const int rbase = bm + wm * 64 + (lane >> 2);
    const int cbase = bn + wn * 32 + (lane & 3) * 2;
#pragma unroll
    for (int mi = 0; mi < 4; mi++) {
#pragma unroll
        for (int ni = 0; ni < 4; ni++) {
            const int col = cbase + ni * 8;
            const float b0 = __ldg(bias + col);
            const float b1 = __ldg(bias + col + 1);
            float* p0 = C + (size_t)(rbase + mi * 16) * N + col;
            float* p1 = C + (size_t)(rbase + mi * 16 + 8) * N + col;
            *(float2*)p0 = make_float2(acc[mi][ni][0] + b0, acc[mi][ni][1] + b1);
            *(float2*)p1 = make_float2(acc[mi][ni][2] + b0, acc[mi][ni][3] + b1);
        }
    }
}

// ---------------------------------------------------------------------------
// Covering-window enumeration
// ---------------------------------------------------------------------------
__device__ __forceinline__ int covers(int r, int lim, int tys[2], int iis[2])
{
    const int th = (r + 1) >> 1;
    const int ih = (r + 1) & 1;
    int n = 0;
    if (th < lim) { tys[n] = th;     iis[n] = ih;     n++; }
    if (th >= 1)  { tys[n] = th - 1; iis[n] = ih + 2; n++; }
    return n;
}

// ---------------------------------------------------------------------------
// Phase 1 (warp per pixel): exp(logits) -> g_E, per-(head,pixel) sums -> g_S
// ---------------------------------------------------------------------------
__global__ __launch_bounds__(256)
void attn_phase1(const float* __restrict__ Q, const float* __restrict__ KV,
                 const float* __restrict__ rel_init,
                 const float* __restrict__ rel_bias)
{
    __shared__ float s_rel[16];
    if (threadIdx.x < 16)
        s_rel[threadIdx.x] = rel_init[threadIdx.x] + rel_bias[threadIdx.x];
    __syncthreads();

    const int wrp  = threadIdx.x >> 5;
    const int lane = threadIdx.x & 31;
    const int pix  = blockIdx.x * 8 + wrp;
    const int b    = pix >> 14;
    const int rc   = pix & (NPIX - 1);
    const int r    = rc >> 7;
    const int c    = rc & (WB - 1);
    const int h    = lane >> 2;
    const int l4   = lane & 3;
    const int ch   = h * 32 + l4 * 8;

    const float* qp = Q + (uint32_t)pix * DIM + ch;
    const float4 q0 = *(const float4*)qp;
    const float4 q1 = *(const float4*)(qp + 4);
    const float* kvbase = KV + (uint32_t)b * (NWIN * KVD) + ch;

    int tys[2], iis[2], txs[2], jjs[2];
    const int nty = covers(r, HT, tys, iis);
    const int ntx = covers(c, WT, txs, jjs);

    float ssum = 0.f;
#pragma unroll
    for (int a = 0; a < 2; a++) {
        if (a >= nty) break;
#pragma unroll
        for (int e = 0; e < 2; e++) {
            if (e >= ntx) break;
            const int w = tys[a] * WT + txs[e];
            const int p = iis[a] * 4 + jjs[e];
            const float* kp = kvbase + w * KVD;
            const float4 k0 = *(const float4*)kp;
            const float4 k1 = *(const float4*)(kp + 4);
            float part = q0.x * k0.x + q0.y * k0.y + q0.z * k0.z + q0.w * k0.w
                       + q1.x * k1.x + q1.y * k1.y + q1.z * k1.z + q1.w * k1.w;
            part += __shfl_xor_sync(0xffffffffu, part, 2);
            part += __shfl_xor_sync(0xffffffffu, part, 1);
            const float ex = expf(part * ATT_SCALE + s_rel[p]);
            ssum += ex;
            if (l4 == 0)
                g_E[(uint32_t)((b * NWIN + w) * HEADS + h) * 16 + p] = ex;
        }
    }
    if (l4 == 0)
        g_S[(uint32_t)(b * HEADS + h) * NPIX + rc] = ssum;
}

// ---------------------------------------------------------------------------
// Phase 2 (warp per pixel, shfl exchange, no smem/barrier): writes split P.
// Scrambled divisor faithful to the reference reshape. OOB slots -> wgt=0.
// ---------------------------------------------------------------------------
__global__ __launch_bounds__(256)
void attn_phase2(const float* __restrict__ KV,
                 __nv_bfloat16* __restrict__ Phi, __nv_bfloat16* __restrict__ Plo)
{
    const int wrp  = threadIdx.x >> 5;
    const int lane = threadIdx.x & 31;
    const int pix  = blockIdx.x * 8 + wrp;
    const int b    = pix >> 14;
    const int rc   = pix & (NPIX - 1);
    const int r    = rc >> 7;
    const int c    = rc & (WB - 1);

    int tys[2], iis[2], txs[2], jjs[2];
    const int nty = covers(r, HT, tys, iis);
    const int ntx = covers(c, WT, txs, jjs);

    const int slot = lane >> 3;
    const int sh   = lane & 7;
    const int sa   = slot >> 1;
    const int se   = slot & 1;
    float wgt = 0.f;
    int   wofs = 0;
    if (sa < nty && se < ntx) {
        const int w = tys[sa] * WT + txs[se];
        const int p = iis[sa] * 4 + jjs[se];
        const float ex = g_E[(uint32_t)((b * NWIN + w) * HEADS + sh) * 16 + p];
        const int h2 = w >> 9;
        const int w2 = ((w & 511) << 3) + sh;
        const int r2 = 2 * (w2 >> 6) - 1 + (p >> 2);
        const int c2 = 2 * (w2 & 63) - 1 + (p & 3);
        float denom = 1.f;
        if ((unsigned)r2 < (unsigned)HB && (unsigned)c2 < (unsigned)WB)
            denom = g_S[(uint32_t)(b * HEADS + h2) * NPIX + r2 * WB + c2];
        wgt = ex / denom;
        wofs = w * KVD;
    }

    const int my_h = lane >> 2;
    float w0 = __shfl_sync(0xffffffffu, wgt, my_h);
    float w1 = __shfl_sync(0xffffffffu, wgt, 8 + my_h);
    float w2_ = __shfl_sync(0xffffffffu, wgt, 16 + my_h);
    float w3 = __shfl_sync(0xffffffffu, wgt, 24 + my_h);
    int o0 = __shfl_sync(0xffffffffu, wofs, 0);
    int o1 = __shfl_sync(0xffffffffu, wofs, 8);
    int o2 = __shfl_sync(0xffffffffu, wofs, 16);
    int o3 = __shfl_sync(0xffffffffu, wofs, 24);

    const float* vbase = KV + (uint32_t)b * (NWIN * KVD) + DIM + lane * 8;
    float4 oa = make_float4(0.f, 0.f, 0.f, 0.f);
    float4 ob = make_float4(0.f, 0.f, 0.f, 0.f);
#pragma unroll
    for (int s = 0; s < 4; s++) {
        const float wg = (s == 0) ? w0 : (s == 1) ? w1 : (s == 2) ? w2_ : w3;
        const int   of = (s == 0) ? o0 : (s == 1) ? o1 : (s == 2) ? o2 : o3;
        const float4 va = *(const float4*)(vbase + of);
        const float4 vb = *(const float4*)(vbase + of + 4);
        oa.x = fmaf(wg, va.x, oa.x); oa.y = fmaf(wg, va.y, oa.y);
        oa.z = fmaf(wg, va.z, oa.z); oa.w = fmaf(wg, va.w, oa.w);
        ob.x = fmaf(wg, vb.x, ob.x); ob.y = fmaf(wg, vb.y, ob.y);
        ob.z = fmaf(wg, vb.z, ob.z); ob.w = fmaf(wg, vb.w, ob.w);
    }

    float xs[8] = {oa.x, oa.y, oa.z, oa.w, ob.x, ob.y, ob.z, ob.w};
    unsigned short hb[8], lb[8];
#pragma unroll
    for (int k = 0; k < 8; k++) {
        __nv_bfloat16 hi = __float2bfloat16(xs[k]);
        __nv_bfloat16 lo = __float2bfloat16(xs[k] - __bfloat162float(hi));
        hb[k] = __bfloat16_as_ushort(hi);
        lb[k] = __bfloat16_as_ushort(lo);
    }
    const uint32_t idx = ((uint32_t)pix * DIM + lane * 8) / 4;
    ((ushort4*)Phi)[idx]     = make_ushort4(hb[0], hb[1], hb[2], hb[3]);
    ((ushort4*)Phi)[idx + 1] = make_ushort4(hb[4], hb[5], hb[6], hb[7]);
    ((ushort4*)Plo)[idx]     = make_ushort4(lb[0], lb[1], lb[2], lb[3]);
    ((ushort4*)Plo)[idx + 1] = make_ushort4(lb[4], lb[5], lb[6], lb[7]);
}

// ---------------------------------------------------------------------------
// Launch (single stream)
// ---------------------------------------------------------------------------
extern "C" void kernel_launch(void* const* d_in, const int* in_sizes, int n_in,
                              void* d_out, int out_size)
{
    (void)in_sizes; (void)n_in; (void)out_size;
    const float* Xt       = (const float*)d_in[0];
    const float* Xb       = (const float*)d_in[1];
    const float* q_w      = (const float*)d_in[2];
    const float* kv_w     = (const float*)d_in[3];
    const float* proj_w   = (const float*)d_in[4];
    const float* proj_b   = (const float*)d_in[5];
    const float* rel_init = (const float*)d_in[6];
    const float* rel_bias = (const float*)d_in[7];
    float* out = (float*)d_out;

    float *Qb, *KVb;
    __nv_bfloat16 *Xbh, *Xbl, *Xth, *Xtl, *Ph, *Pl;
    __nv_bfloat16 *wqh, *wql, *wkh, *wkl, *wph, *wpl;
    cudaGetSymbolAddress((void**)&Qb,  g_Q);
    cudaGetSymbolAddress((void**)&KVb, g_KV);
    cudaGetSymbolAddress((void**)&Xbh, g_Xbh);
    cudaGetSymbolAddress((void**)&Xbl, g_Xbl);
    cudaGetSymbolAddress((void**)&Xth, g_Xth);
    cudaGetSymbolAddress((void**)&Xtl, g_Xtl);
    cudaGetSymbolAddress((void**)&Ph,  g_Ph);
    cudaGetSymbolAddress((void**)&Pl,  g_Pl);
    cudaGetSymbolAddress((void**)&wqh, g_wqh);
    cudaGetSymbolAddress((void**)&wql, g_wql);
    cudaGetSymbolAddress((void**)&wkh, g_wkh);
    cudaGetSymbolAddress((void**)&wkl, g_wkl);
    cudaGetSymbolAddress((void**)&wph, g_wph);
    cudaGetSymbolAddress((void**)&wpl, g_wpl);

    cudaFuncSetAttribute(gemm_qkv,
                         cudaFuncAttributeMaxDynamicSharedMemorySize, GEMM_SMEM);
    cudaFuncSetAttribute(gemm_proj,
                         cudaFuncAttributeMaxDynamicSharedMemorySize, PROJ_SMEM);

    // fused splits
    split_all<<<(S4 / 2 + 255) / 256, 256>>>(Xb, Xt, q_w, kv_w, proj_w,
                                             Xbh, Xbl, Xth, Xtl,
                                             wqh, wql, wkh, wkl, wph, wpl);

    // 1+2) KV = Xt @ kv_w^T (long tiles first) and Q = Xb @ q_w^T
    gemm_qkv<<<QBLKS + KVBLKS, 128, GEMM_SMEM>>>(
        Xbh, Xbl, wqh, wql, Xth, Xtl, wkh, wkl, Qb, KVb);

    // 3) attention numerators + sums (warp per pixel)
    attn_phase1<<<(BATCH * NPIX) / 8, 256>>>(Qb, KVb, rel_init, rel_bias);

    // 4) normalization + V + fold (warp per pixel, writes split P)
    attn_phase2<<<(BATCH * NPIX) / 8, 256>>>(KVb, Ph, Pl);

    // 5) Out = P @ proj_w^T + proj_b  (TBN=64 variant, small tail)
    gemm_proj<<<dim3(DIM / PTBN, (BATCH * NPIX) / TBM), 128, PROJ_SMEM>>>(
        Ph, Pl, wph, wpl, proj_b, out);
}